// round 3
// baseline (speedup 1.0000x reference)
#include <cuda_runtime.h>
#include <math_constants.h>
#include <cstdint>

#define B  4
#define N  16384
#define S  4096
#define C  256

#define CHUNKS 2
#define SKEYS  (S / CHUNKS)     // 2048 keys per chunk
#define SPAIRS (SKEYS / 2)      // 1024 pairs (32 KB smem)
#define QPT    4                // queries per thread
#define KT     128              // threads per knn block -> 512 queries/block

// Scratch: per-chunk partial top-3 (allocation-free rule -> device globals)
__device__ float p_d[B * N * CHUNKS * 3];
__device__ int   p_i[B * N * CHUNKS * 3];

// ---------------------------------------------------------------------------
// f32x2 packed helpers (sm_103a FFMA2/FADD2 only reachable via PTX f32x2)
// ---------------------------------------------------------------------------
__device__ __forceinline__ uint64_t fma2_(uint64_t a, uint64_t b, uint64_t c) {
    uint64_t d;
    asm("fma.rn.f32x2 %0, %1, %2, %3;" : "=l"(d) : "l"(a), "l"(b), "l"(c));
    return d;
}
__device__ __forceinline__ uint64_t add2_(uint64_t a, uint64_t b) {
    uint64_t d;
    asm("add.rn.f32x2 %0, %1, %2;" : "=l"(d) : "l"(a), "l"(b));
    return d;
}
__device__ __forceinline__ uint64_t pack2_(float lo, float hi) {
    uint64_t d;
    asm("mov.b64 %0, {%1, %2};" : "=l"(d) : "f"(lo), "f"(hi));
    return d;
}
__device__ __forceinline__ void unpack2_(uint64_t v, float& lo, float& hi) {
    asm("mov.b64 {%0, %1}, %2;" : "=f"(lo), "=f"(hi) : "l"(v));
}

// Strict-< insert keeps earliest index on ties (matches jax.lax.top_k)
#define INSERT3(D0, D1, D2, I0, I1, I2, d, s) do {                       \
    if ((d) < (D1)) {                                                    \
        (D2) = (D1); (I2) = (I1);                                        \
        if ((d) < (D0)) { (D1)=(D0); (I1)=(I0); (D0)=(d); (I0)=(s); }    \
        else            { (D1)=(d);  (I1)=(s); }                         \
    } else { (D2) = (d); (I2) = (s); }                                   \
} while (0)

// ---------------------------------------------------------------------------
// Phase 1: partial 3-NN over a 2048-key chunk, 4 queries per thread.
// Keys in smem as packed pairs: kp[2p] = {x2,y2}, kp[2p+1] = {z2,w2}.
// Per pair: 2 LDS.128 amortized over 4 queries; per query 1 FADD2 + 3 FFMA2
// + FMNMX + FSETP + rarely-taken insert branch.
// ---------------------------------------------------------------------------
__global__ void __launch_bounds__(KT) knn_kernel(const float* __restrict__ q,
                                                 const float* __restrict__ k)
{
    __shared__ ulonglong2 kp[SPAIRS * 2];   // 32 KB

    const int b     = blockIdx.z;
    const int chunk = blockIdx.y;
    const int tid   = threadIdx.x;
    const int nblk  = blockIdx.x * (KT * QPT);

    // Cooperative load: packed pair layout + ||k||^2
    const float* kb = k + ((size_t)b * S + (size_t)chunk * SKEYS) * 3;
    for (int p = tid; p < SPAIRS; p += KT) {
        float x0 = kb[6 * p + 0], y0 = kb[6 * p + 1], z0 = kb[6 * p + 2];
        float x1 = kb[6 * p + 3], y1 = kb[6 * p + 4], z1 = kb[6 * p + 5];
        float w0 = fmaf(x0, x0, fmaf(y0, y0, z0 * z0));
        float w1 = fmaf(x1, x1, fmaf(y1, y1, z1 * z1));
        kp[2 * p]     = make_ulonglong2(pack2_(x0, x1), pack2_(y0, y1));
        kp[2 * p + 1] = make_ulonglong2(pack2_(z0, z1), pack2_(w0, w1));
    }
    __syncthreads();

    // Per-thread query set: nblk + tid + 128*j  (coalesced q loads per j)
    uint64_t ax2[QPT], ay2[QPT], az2[QPT], qq2[QPT];
    float d0[QPT], d1[QPT], d2[QPT];
    int   i0[QPT], i1[QPT], i2[QPT];
#pragma unroll
    for (int j = 0; j < QPT; ++j) {
        const int n = nblk + tid + j * KT;
        const float* qp = q + ((size_t)b * N + n) * 3;
        const float qx = qp[0], qy = qp[1], qz = qp[2];
        const float qq = fmaf(qx, qx, fmaf(qy, qy, qz * qz));
        ax2[j] = pack2_(-2.0f * qx, -2.0f * qx);
        ay2[j] = pack2_(-2.0f * qy, -2.0f * qy);
        az2[j] = pack2_(-2.0f * qz, -2.0f * qz);
        qq2[j] = pack2_(qq, qq);
        d0[j] = CUDART_INF_F; d1[j] = CUDART_INF_F; d2[j] = CUDART_INF_F;
        i0[j] = 0; i1[j] = 0; i2[j] = 0;
    }

#pragma unroll 2
    for (int p = 0; p < SPAIRS; ++p) {
        const ulonglong2 A = kp[2 * p];       // {x-pair, y-pair}
        const ulonglong2 Z = kp[2 * p + 1];   // {z-pair, w-pair}
#pragma unroll
        for (int j = 0; j < QPT; ++j) {
            uint64_t t = add2_(qq2[j], Z.y);
            t = fma2_(az2[j], Z.x, t);
            t = fma2_(ay2[j], A.y, t);
            t = fma2_(ax2[j], A.x, t);
            float ta, tb;
            unpack2_(t, ta, tb);
            if (fminf(ta, tb) < d2[j]) {
                if (ta < d2[j]) INSERT3(d0[j], d1[j], d2[j], i0[j], i1[j], i2[j], ta, 2 * p);
                if (tb < d2[j]) INSERT3(d0[j], d1[j], d2[j], i0[j], i1[j], i2[j], tb, 2 * p + 1);
            }
        }
    }

    const int off = chunk * SKEYS;
#pragma unroll
    for (int j = 0; j < QPT; ++j) {
        const int n = nblk + tid + j * KT;
        const int base = ((b * N + n) * CHUNKS + chunk) * 3;
        p_d[base + 0] = d0[j];  p_i[base + 0] = i0[j] + off;
        p_d[base + 1] = d1[j];  p_i[base + 1] = i1[j] + off;
        p_d[base + 2] = d2[j];  p_i[base + 2] = i2[j] + off;
    }
}

// ---------------------------------------------------------------------------
// Phase 2: merge 2 partial triples + weighted gather + transpose.
// All smem traffic conflict-free: stride-257 rows, warp = 32 consecutive
// channels for coalesced LDG/STS; transposed STG 128B-contiguous along n.
// ---------------------------------------------------------------------------
#define NQ 32

__global__ void __launch_bounds__(256) gather_kernel(const float* __restrict__ v,
                                                     float* __restrict__ out)
{
    __shared__ float buf[NQ][C + 1];   // 257 mod 32 = 1 -> conflict-free both ways
    __shared__ float w[NQ * 3];
    __shared__ int   id[NQ * 3];

    const int b   = blockIdx.y;
    const int n0  = blockIdx.x * NQ;
    const int tid = threadIdx.x;       // 256 threads

    if (tid < NQ) {
        const int base = ((b * N + n0 + tid) * CHUNKS) * 3;
        float d0 = p_d[base + 0], d1 = p_d[base + 1], d2 = p_d[base + 2];
        int   i0 = p_i[base + 0], i1 = p_i[base + 1], i2 = p_i[base + 2];
#pragma unroll
        for (int j = 3; j < CHUNKS * 3; ++j) {
            const float d = p_d[base + j];
            const int   s = p_i[base + j];
            if (d < d2) { INSERT3(d0, d1, d2, i0, i1, i2, d, s); }
        }
        const float r0 = 1.0f / (d0 + 1e-8f);
        const float r1 = 1.0f / (d1 + 1e-8f);
        const float r2 = 1.0f / (d2 + 1e-8f);
        const float inv = 1.0f / (r0 + r1 + r2);
        w[tid * 3 + 0] = r0 * inv;  id[tid * 3 + 0] = i0;
        w[tid * 3 + 1] = r1 * inv;  id[tid * 3 + 1] = i1;
        w[tid * 3 + 2] = r2 * inv;  id[tid * 3 + 2] = i2;
    }
    __syncthreads();

    const float* vb = v + (size_t)b * S * C;

    // Gather: one query per iteration; 256 threads = all channels.
#pragma unroll 4
    for (int ql = 0; ql < NQ; ++ql) {
        const int   j0 = id[ql * 3 + 0], j1 = id[ql * 3 + 1], j2 = id[ql * 3 + 2];
        const float w0 = w[ql * 3 + 0],  w1 = w[ql * 3 + 1],  w2 = w[ql * 3 + 2];
        const float a0 = vb[j0 * C + tid];
        const float a1 = vb[j1 * C + tid];
        const float a2 = vb[j2 * C + tid];
        buf[ql][tid] = fmaf(w0, a0, fmaf(w1, a1, w2 * a2));
    }
    __syncthreads();

    // Transposed write: warp -> channel rows, lanes -> 32 consecutive n.
    const int warp = tid >> 5;
    const int lane = tid & 31;
    float* ob = out + (size_t)b * C * N + n0;
#pragma unroll
    for (int c = warp; c < C; c += 8)
        ob[c * N + lane] = buf[lane][c];
}

// ---------------------------------------------------------------------------
extern "C" void kernel_launch(void* const* d_in, const int* in_sizes, int n_in,
                              void* d_out, int out_size)
{
    const float* q = (const float*)d_in[0];   // (B, N, 3)
    const float* k = (const float*)d_in[1];   // (B, S, 3)
    const float* v = (const float*)d_in[2];   // (B, S, C)
    float* out = (float*)d_out;               // (B, C, N)

    dim3 g1(N / (KT * QPT), CHUNKS, B);       // 32 x 2 x 4 = 256 blocks
    knn_kernel<<<g1, KT>>>(q, k);

    dim3 g2(N / NQ, B);                       // 512 x 4 = 2048 blocks
    gather_kernel<<<g2, 256>>>(v, out);
}

// round 4
// speedup vs baseline: 1.7527x; 1.7527x over previous
#include <cuda_runtime.h>
#include <math_constants.h>
#include <cstdint>

#define B  4
#define N  16384
#define S  4096
#define C  256

#define CHUNKS 4
#define SKEYS  (S / CHUNKS)     // 1024 keys per chunk
#define SPAIRS (SKEYS / 2)      // 512 pairs (16 KB smem)
#define QT     256              // queries per knn block

// Scratch: per-chunk partial top-3 (allocation-free rule -> device globals)
__device__ float p_d[B * N * CHUNKS * 3];
__device__ int   p_i[B * N * CHUNKS * 3];

// ---------------------------------------------------------------------------
// f32x2 packed helpers (sm_103a FFMA2/FADD2 only reachable via PTX f32x2)
// ---------------------------------------------------------------------------
__device__ __forceinline__ uint64_t fma2_(uint64_t a, uint64_t b, uint64_t c) {
    uint64_t d;
    asm("fma.rn.f32x2 %0, %1, %2, %3;" : "=l"(d) : "l"(a), "l"(b), "l"(c));
    return d;
}
__device__ __forceinline__ uint64_t add2_(uint64_t a, uint64_t b) {
    uint64_t d;
    asm("add.rn.f32x2 %0, %1, %2;" : "=l"(d) : "l"(a), "l"(b));
    return d;
}
__device__ __forceinline__ uint64_t pack2_(float lo, float hi) {
    uint64_t d;
    asm("mov.b64 %0, {%1, %2};" : "=l"(d) : "f"(lo), "f"(hi));
    return d;
}
__device__ __forceinline__ void unpack2_(uint64_t v, float& lo, float& hi) {
    asm("mov.b64 {%0, %1}, %2;" : "=f"(lo), "=f"(hi) : "l"(v));
}

// Branch-free sorted-3 insert (strict < keeps earliest index on ties,
// matching jax.lax.top_k). Pure select chains -> FSETP + FSEL/SEL, no BSSY.
#define FLAT_INSERT(d, s) do {                                   \
    const bool q0 = (d) < d0;                                    \
    const bool q1 = (d) < d1;                                    \
    const bool q2 = (d) < d2;                                    \
    const float od1 = d1; const int oi1 = i1;                    \
    const float od0 = d0; const int oi0 = i0;                    \
    d2 = q2 ? (q1 ? od1 : (d)) : d2;                             \
    i2 = q2 ? (q1 ? oi1 : (s)) : i2;                             \
    d1 = q1 ? (q0 ? od0 : (d)) : d1;                             \
    i1 = q1 ? (q0 ? oi0 : (s)) : i1;                             \
    d0 = q0 ? (d) : d0;                                          \
    i0 = q0 ? (s) : i0;                                          \
} while (0)

// Nested insert for the (non-hot) merge in gather
#define INSERT3(d, s) do {                                       \
    if ((d) < d1) {                                              \
        d2 = d1; i2 = i1;                                        \
        if ((d) < d0) { d1 = d0; i1 = i0; d0 = (d); i0 = (s); }  \
        else          { d1 = (d); i1 = (s); }                    \
    } else { d2 = (d); i2 = (s); }                               \
} while (0)

// ---------------------------------------------------------------------------
// Phase 1: brute-force partial 3-NN over a 1024-key chunk, 1 query/thread.
// Keys in smem packed as pairs: kp[2p] = {x2,y2}, kp[2p+1] = {z2,w2}.
// Hot path/pair: 2 LDS.128 + 1 FADD2 + 3 FFMA2 + FMNMX + FSETP + rare branch
// whose body is a single flat predicated region (no nested divergence).
// ---------------------------------------------------------------------------
__global__ void __launch_bounds__(QT) knn_kernel(const float* __restrict__ q,
                                                 const float* __restrict__ k)
{
    __shared__ ulonglong2 kp[SPAIRS * 2];   // 16 KB

    const int b     = blockIdx.z;
    const int chunk = blockIdx.y;
    const int n     = blockIdx.x * QT + threadIdx.x;

    // Cooperative load: packed pair layout + ||k||^2
    const float* kb = k + ((size_t)b * S + (size_t)chunk * SKEYS) * 3;
    for (int p = threadIdx.x; p < SPAIRS; p += QT) {
        float x0 = kb[6 * p + 0], y0 = kb[6 * p + 1], z0 = kb[6 * p + 2];
        float x1 = kb[6 * p + 3], y1 = kb[6 * p + 4], z1 = kb[6 * p + 5];
        float w0 = fmaf(x0, x0, fmaf(y0, y0, z0 * z0));
        float w1 = fmaf(x1, x1, fmaf(y1, y1, z1 * z1));
        kp[2 * p]     = make_ulonglong2(pack2_(x0, x1), pack2_(y0, y1));
        kp[2 * p + 1] = make_ulonglong2(pack2_(z0, z1), pack2_(w0, w1));
    }
    __syncthreads();

    const float* qp = q + ((size_t)b * N + n) * 3;
    const float qx = qp[0], qy = qp[1], qz = qp[2];
    const float qq = fmaf(qx, qx, fmaf(qy, qy, qz * qz));
    const uint64_t ax2 = pack2_(-2.0f * qx, -2.0f * qx);
    const uint64_t ay2 = pack2_(-2.0f * qy, -2.0f * qy);
    const uint64_t az2 = pack2_(-2.0f * qz, -2.0f * qz);
    const uint64_t qq2 = pack2_(qq, qq);

    float d0 = CUDART_INF_F, d1 = CUDART_INF_F, d2 = CUDART_INF_F;
    int   i0 = 0, i1 = 0, i2 = 0;

#pragma unroll 4
    for (int p = 0; p < SPAIRS; ++p) {
        const ulonglong2 A = kp[2 * p];       // {x-pair, y-pair}
        const ulonglong2 Z = kp[2 * p + 1];   // {z-pair, w-pair}
        uint64_t t = add2_(qq2, Z.y);
        t = fma2_(az2, Z.x, t);
        t = fma2_(ay2, A.y, t);
        t = fma2_(ax2, A.x, t);
        float ta, tb;
        unpack2_(t, ta, tb);
        if (fminf(ta, tb) < d2) {
            // Flat predicated body: insert both candidates, index order
            // 2p before 2p+1 (preserves earliest-index tie-break).
            FLAT_INSERT(ta, 2 * p);
            FLAT_INSERT(tb, 2 * p + 1);
        }
    }

    const int base = ((b * N + n) * CHUNKS + chunk) * 3;
    const int off  = chunk * SKEYS;
    p_d[base + 0] = d0;  p_i[base + 0] = i0 + off;
    p_d[base + 1] = d1;  p_i[base + 1] = i1 + off;
    p_d[base + 2] = d2;  p_i[base + 2] = i2 + off;
}

// ---------------------------------------------------------------------------
// Phase 2: merge partial top-3 + weighted gather (float4) + transpose.
// ---------------------------------------------------------------------------
#define NQ 32

__global__ void __launch_bounds__(256) gather_kernel(const float* __restrict__ v,
                                                     float* __restrict__ out)
{
    __shared__ float buf[NQ][C + 4];   // rows 16B-aligned for STS.128
    __shared__ float w[NQ * 3];
    __shared__ int   id[NQ * 3];

    const int b   = blockIdx.y;
    const int n0  = blockIdx.x * NQ;
    const int tid = threadIdx.x;       // 256 threads

    if (tid < NQ) {
        const int base = ((b * N + n0 + tid) * CHUNKS) * 3;
        float d0 = p_d[base + 0], d1 = p_d[base + 1], d2 = p_d[base + 2];
        int   i0 = p_i[base + 0], i1 = p_i[base + 1], i2 = p_i[base + 2];
#pragma unroll
        for (int j = 3; j < CHUNKS * 3; ++j) {
            const float d = p_d[base + j];
            const int   s = p_i[base + j];
            if (d < d2) { INSERT3(d, s); }
        }
        const float r0 = 1.0f / (d0 + 1e-8f);
        const float r1 = 1.0f / (d1 + 1e-8f);
        const float r2 = 1.0f / (d2 + 1e-8f);
        const float inv = 1.0f / (r0 + r1 + r2);
        w[tid * 3 + 0] = r0 * inv;  id[tid * 3 + 0] = i0;
        w[tid * 3 + 1] = r1 * inv;  id[tid * 3 + 1] = i1;
        w[tid * 3 + 2] = r2 * inv;  id[tid * 3 + 2] = i2;
    }
    __syncthreads();

    const float4* vb4 = (const float4*)(v + (size_t)b * S * C);
    const int c4 = tid & 63;          // float4 channel slot (64 per row)
    const int qo = tid >> 6;          // 4 queries per iteration

#pragma unroll
    for (int qb = 0; qb < NQ; qb += 4) {
        const int ql = qb + qo;
        const int   j0 = id[ql * 3 + 0], j1 = id[ql * 3 + 1], j2 = id[ql * 3 + 2];
        const float w0 = w[ql * 3 + 0],  w1 = w[ql * 3 + 1],  w2 = w[ql * 3 + 2];
        const float4 a0 = vb4[j0 * 64 + c4];
        const float4 a1 = vb4[j1 * 64 + c4];
        const float4 a2 = vb4[j2 * 64 + c4];
        float4 r;
        r.x = fmaf(w0, a0.x, fmaf(w1, a1.x, w2 * a2.x));
        r.y = fmaf(w0, a0.y, fmaf(w1, a1.y, w2 * a2.y));
        r.z = fmaf(w0, a0.z, fmaf(w1, a1.z, w2 * a2.z));
        r.w = fmaf(w0, a0.w, fmaf(w1, a1.w, w2 * a2.w));
        *(float4*)&buf[ql][c4 * 4] = r;   // STS.128 (16B-aligned rows)
    }
    __syncthreads();

    // Transposed write: warp -> channel rows, lanes -> 32 consecutive n.
    const int warp = tid >> 5;
    const int lane = tid & 31;
    float* ob = out + (size_t)b * C * N + n0;
#pragma unroll
    for (int c = warp; c < C; c += 8)
        ob[c * N + lane] = buf[lane][c];
}

// ---------------------------------------------------------------------------
extern "C" void kernel_launch(void* const* d_in, const int* in_sizes, int n_in,
                              void* d_out, int out_size)
{
    const float* q = (const float*)d_in[0];   // (B, N, 3)
    const float* k = (const float*)d_in[1];   // (B, S, 3)
    const float* v = (const float*)d_in[2];   // (B, S, C)
    float* out = (float*)d_out;               // (B, C, N)

    dim3 g1(N / QT, CHUNKS, B);               // 64 x 4 x 4 = 1024 blocks
    knn_kernel<<<g1, QT>>>(q, k);

    dim3 g2(N / NQ, B);                       // 512 x 4 = 2048 blocks
    gather_kernel<<<g2, 256>>>(v, out);
}

// round 5
// speedup vs baseline: 1.8173x; 1.0369x over previous
#include <cuda_runtime.h>
#include <math_constants.h>
#include <cstdint>

#define B  4
#define N  16384
#define S  4096
#define C  256

#define SPAIRS (S / 2)          // 2048 pairs, full key set (64 KB smem)
#define QT     256              // queries per knn block

// Final per-query weights + indices (allocation-free rule -> device globals)
__device__ float g_w[B * N * 3];
__device__ int   g_i[B * N * 3];

// ---------------------------------------------------------------------------
// f32x2 packed helpers (sm_103a FFMA2 only reachable via PTX f32x2)
// ---------------------------------------------------------------------------
__device__ __forceinline__ uint64_t fma2_(uint64_t a, uint64_t b, uint64_t c) {
    uint64_t d;
    asm("fma.rn.f32x2 %0, %1, %2, %3;" : "=l"(d) : "l"(a), "l"(b), "l"(c));
    return d;
}
__device__ __forceinline__ uint64_t pack2_(float lo, float hi) {
    uint64_t d;
    asm("mov.b64 %0, {%1, %2};" : "=l"(d) : "f"(lo), "f"(hi));
    return d;
}
__device__ __forceinline__ void unpack2_(uint64_t v, float& lo, float& hi) {
    asm("mov.b64 {%0, %1}, %2;" : "=f"(lo), "=f"(hi) : "l"(v));
}

// Branch-free sorted-3 insert; strict < keeps earliest index on ties
// (matches jax.lax.top_k). Compiles to FSETP + select chains, no BSSY.
#define FLAT_INSERT(d, s) do {                                   \
    const bool q0 = (d) < d0;                                    \
    const bool q1 = (d) < d1;                                    \
    const bool q2 = (d) < d2;                                    \
    const float od1 = d1; const int oi1 = i1;                    \
    const float od0 = d0; const int oi0 = i0;                    \
    d2 = q2 ? (q1 ? od1 : (d)) : d2;                             \
    i2 = q2 ? (q1 ? oi1 : (s)) : i2;                             \
    d1 = q1 ? (q0 ? od0 : (d)) : d1;                             \
    i1 = q1 ? (q0 ? oi0 : (s)) : i1;                             \
    d0 = q0 ? (d) : d0;                                          \
    i0 = q0 ? (s) : i0;                                          \
} while (0)

// ---------------------------------------------------------------------------
// Phase 1: single-pass brute-force 3-NN over all 4096 keys, 1 query/thread.
// Keys in smem packed as pairs: kp[2p] = {x2,y2}, kp[2p+1] = {z2,kk2}.
// d' = kk - 2*q.k (qq constant dropped: top-k invariant; re-added for weights).
// Hot path/pair: 2 LDS.128 + 3 FFMA2 + FMNMX + FSETP + rare branch; body is
// one flat insert of the pair-min + an even rarer second insert.
// ---------------------------------------------------------------------------
__global__ void __launch_bounds__(QT) knn_kernel(const float* __restrict__ q,
                                                 const float* __restrict__ k)
{
    extern __shared__ ulonglong2 kp[];   // SPAIRS*2 entries = 64 KB

    const int b = blockIdx.y;
    const int n = blockIdx.x * QT + threadIdx.x;

    // Cooperative load: packed pair layout + ||k||^2
    const float* kb = k + (size_t)b * S * 3;
    for (int p = threadIdx.x; p < SPAIRS; p += QT) {
        float x0 = kb[6 * p + 0], y0 = kb[6 * p + 1], z0 = kb[6 * p + 2];
        float x1 = kb[6 * p + 3], y1 = kb[6 * p + 4], z1 = kb[6 * p + 5];
        float w0 = fmaf(x0, x0, fmaf(y0, y0, z0 * z0));
        float w1 = fmaf(x1, x1, fmaf(y1, y1, z1 * z1));
        kp[2 * p]     = make_ulonglong2(pack2_(x0, x1), pack2_(y0, y1));
        kp[2 * p + 1] = make_ulonglong2(pack2_(z0, z1), pack2_(w0, w1));
    }
    __syncthreads();

    const float* qp = q + ((size_t)b * N + n) * 3;
    const float qx = qp[0], qy = qp[1], qz = qp[2];
    const float qq = fmaf(qx, qx, fmaf(qy, qy, qz * qz));
    const uint64_t ax2 = pack2_(-2.0f * qx, -2.0f * qx);
    const uint64_t ay2 = pack2_(-2.0f * qy, -2.0f * qy);
    const uint64_t az2 = pack2_(-2.0f * qz, -2.0f * qz);

    float d0 = CUDART_INF_F, d1 = CUDART_INF_F, d2 = CUDART_INF_F;
    int   i0 = 0, i1 = 0, i2 = 0;

#pragma unroll 4
    for (int p = 0; p < SPAIRS; ++p) {
        const ulonglong2 A = kp[2 * p];       // {x-pair, y-pair}
        const ulonglong2 Z = kp[2 * p + 1];   // {z-pair, kk-pair}
        uint64_t t = fma2_(az2, Z.x, Z.y);    // kk - 2qz*z
        t = fma2_(ay2, A.y, t);
        t = fma2_(ax2, A.x, t);
        float ta, tb;
        unpack2_(t, ta, tb);
        const float dm = fminf(ta, tb);
        if (dm < d2) {
            // ta<=tb picks index 2p first: preserves earliest-index ties
            const bool afirst = (ta <= tb);
            const int sm = afirst ? 2 * p : 2 * p + 1;
            FLAT_INSERT(dm, sm);
            const float dx = fmaxf(ta, tb);
            if (dx < d2) {                    // both candidates qualify: rare
                const int sx = afirst ? 2 * p + 1 : 2 * p;
                FLAT_INSERT(dx, sx);
            }
        }
    }

    // True distances = d' + qq; weights = normalized reciprocals
    const float r0 = 1.0f / (d0 + qq + 1e-8f);
    const float r1 = 1.0f / (d1 + qq + 1e-8f);
    const float r2 = 1.0f / (d2 + qq + 1e-8f);
    const float inv = 1.0f / (r0 + r1 + r2);

    const int base = (b * N + n) * 3;
    g_w[base + 0] = r0 * inv;  g_i[base + 0] = i0;
    g_w[base + 1] = r1 * inv;  g_i[base + 1] = i1;
    g_w[base + 2] = r2 * inv;  g_i[base + 2] = i2;
}

// ---------------------------------------------------------------------------
// Phase 2: weighted gather (float4 rows of v) + transpose to out[b][c][n].
// NQ=16 -> 17 KB smem -> 8 blocks/SM (occ 100%) for more memory parallelism.
// ---------------------------------------------------------------------------
#define NQ 16

__global__ void __launch_bounds__(256) gather_kernel(const float* __restrict__ v,
                                                     float* __restrict__ out)
{
    __shared__ float buf[NQ][C + 4];   // rows 16B-aligned for STS.128
    __shared__ float w[NQ * 3];
    __shared__ int   id[NQ * 3];

    const int b   = blockIdx.y;
    const int n0  = blockIdx.x * NQ;
    const int tid = threadIdx.x;       // 256 threads

    if (tid < NQ * 3) {
        const int base = (b * N + n0) * 3;
        w[tid]  = g_w[base + tid];
        id[tid] = g_i[base + tid];
    }
    __syncthreads();

    const float4* vb4 = (const float4*)(v + (size_t)b * S * C);
    const int c4 = tid & 63;          // float4 channel slot (64 per row)
    const int qo = tid >> 6;          // 4 queries per iteration

#pragma unroll
    for (int qb = 0; qb < NQ; qb += 4) {
        const int ql = qb + qo;
        const int   j0 = id[ql * 3 + 0], j1 = id[ql * 3 + 1], j2 = id[ql * 3 + 2];
        const float w0 = w[ql * 3 + 0],  w1 = w[ql * 3 + 1],  w2 = w[ql * 3 + 2];
        const float4 a0 = vb4[j0 * 64 + c4];
        const float4 a1 = vb4[j1 * 64 + c4];
        const float4 a2 = vb4[j2 * 64 + c4];
        float4 r;
        r.x = fmaf(w0, a0.x, fmaf(w1, a1.x, w2 * a2.x));
        r.y = fmaf(w0, a0.y, fmaf(w1, a1.y, w2 * a2.y));
        r.z = fmaf(w0, a0.z, fmaf(w1, a1.z, w2 * a2.z));
        r.w = fmaf(w0, a0.w, fmaf(w1, a1.w, w2 * a2.w));
        *(float4*)&buf[ql][c4 * 4] = r;   // STS.128 (16B-aligned rows)
    }
    __syncthreads();

    // Transposed write: each warp covers 2 channels per iter (16 n per half-warp)
    const int lane = tid & 31;
    const int warp = tid >> 5;
    const int nloc = lane & 15;
    const int csub = lane >> 4;       // 0/1: which of the warp's 2 channels
    float* ob = out + (size_t)b * C * N + n0;
#pragma unroll
    for (int it = 0; it < 16; ++it) {
        const int c = it * 16 + warp * 2 + csub;
        ob[c * N + nloc] = buf[nloc][c];
    }
}

// ---------------------------------------------------------------------------
extern "C" void kernel_launch(void* const* d_in, const int* in_sizes, int n_in,
                              void* d_out, int out_size)
{
    const float* q = (const float*)d_in[0];   // (B, N, 3)
    const float* k = (const float*)d_in[1];   // (B, S, 3)
    const float* v = (const float*)d_in[2];   // (B, S, C)
    float* out = (float*)d_out;               // (B, C, N)

    static_assert(SPAIRS * 2 * sizeof(ulonglong2) == 65536, "smem size");
    cudaFuncSetAttribute(knn_kernel,
                         cudaFuncAttributeMaxDynamicSharedMemorySize, 65536);

    dim3 g1(N / QT, B);                       // 64 x 4 = 256 blocks, all resident
    knn_kernel<<<g1, QT, 65536>>>(q, k);

    dim3 g2(N / NQ, B);                       // 1024 x 4 = 4096 blocks
    gather_kernel<<<g2, 256>>>(v, out);
}